// round 16
// baseline (speedup 1.0000x reference)
#include <cuda_runtime.h>
#include <cuda_bf16.h>
#include <math.h>

#define Bz 2
#define Sz 2048
#define Dz 512
#define Hz 8
#define DPH 64
#define BHn (Bz*Hz)
#define Mrows (Bz*Sz)
#define QT 128
#define NQT (Sz/QT)
#define NX ((size_t)Mrows*Dz)
#define NW ((size_t)Dz*Dz)

__device__ __nv_bfloat16 gXhi[3][NX];
__device__ __nv_bfloat16 gXlo[3][NX];
__device__ __nv_bfloat16 gWhi[3][NW];
__device__ __nv_bfloat16 gWlo[3][NW];
__device__ __nv_bfloat16 gPhi[3][(size_t)BHn*Sz*DPH];
__device__ __nv_bfloat16 gPlo[3][(size_t)BHn*Sz*DPH];
__device__ float g_l[BHn*Sz];

// ===================== helpers =====================
__device__ __forceinline__ unsigned smem_u32(const void* p) {
    unsigned a;
    asm("{ .reg .u64 t; cvta.to.shared.u64 t, %1; cvt.u32.u64 %0, t; }" : "=r"(a) : "l"(p));
    return a;
}
#define SWZ(x) ((x) ^ (((x) >> 3) & 0x70))
__device__ __forceinline__ float tobf(float x) { return __bfloat162float(__float2bfloat16_rn(x)); }
__device__ __forceinline__ unsigned pk(float a, float b) {
    __nv_bfloat162 t = __floats2bfloat162_rn(a, b);
    return *(unsigned*)&t;
}
__device__ __forceinline__ void ldsm4(unsigned addr, unsigned& r0, unsigned& r1, unsigned& r2, unsigned& r3) {
    asm volatile("ldmatrix.sync.aligned.m8n8.x4.shared.b16 {%0,%1,%2,%3}, [%4];"
        : "=r"(r0), "=r"(r1), "=r"(r2), "=r"(r3) : "r"(addr));
}
__device__ __forceinline__ void ldsm4t(unsigned addr, unsigned& r0, unsigned& r1, unsigned& r2, unsigned& r3) {
    asm volatile("ldmatrix.sync.aligned.m8n8.x4.trans.shared.b16 {%0,%1,%2,%3}, [%4];"
        : "=r"(r0), "=r"(r1), "=r"(r2), "=r"(r3) : "r"(addr));
}
__device__ __forceinline__ void mma16816(float* c, const unsigned* a, unsigned b0, unsigned b1) {
    asm volatile("mma.sync.aligned.m16n8k16.row.col.f32.bf16.bf16.f32 "
        "{%0,%1,%2,%3},{%4,%5,%6,%7},{%8,%9},{%0,%1,%2,%3};"
        : "+f"(c[0]), "+f"(c[1]), "+f"(c[2]), "+f"(c[3])
        : "r"(a[0]), "r"(a[1]), "r"(a[2]), "r"(a[3]), "r"(b0), "r"(b1));
}
__device__ __forceinline__ void cpa(unsigned dst, const void* src) {
    asm volatile("cp.async.cg.shared.global [%0], [%1], 16;" :: "r"(dst), "l"(src));
}
#define CP_COMMIT() asm volatile("cp.async.commit_group;" ::: "memory")
#define CP_WAIT(n)  asm volatile("cp.async.wait_group %0;" :: "n"(n) : "memory")

// attn smem: Q 32KB + 2 stages x 64KB
#define SM_QHI 0u
#define SM_QLO 16384u
#define SM_KV  32768u
#define SMEM_ATTN (32768 + 2*65536 + 1024)
// pass2 smem: Q 32KB + 1 stage x 32KB (KHI,KLO) -> 2 CTAs/SM
#define SMEM_P2 (32768 + 32768 + 1024)
// proj smem: 2 stages x 64KB
#define SMEM_PROJ (131072 + 1024)

// ---------------------------------------------------------------------------
__global__ __launch_bounds__(256) void split_kernel(
    const float* __restrict__ q, const float* __restrict__ k, const float* __restrict__ v,
    const float* __restrict__ wq, const float* __restrict__ wk, const float* __restrict__ wv)
{
    const int z = blockIdx.y;
    const float* src = (z==0)?q:(z==1)?k:(z==2)?v:(z==3)?wq:(z==4)?wk:wv;
    __nv_bfloat16* dh; __nv_bfloat16* dl; size_t n4;
    if (z < 3) { dh = gXhi[z]; dl = gXlo[z]; n4 = NX/4; }
    else       { dh = gWhi[z-3]; dl = gWlo[z-3]; n4 = NW/4; }
    for (size_t i = blockIdx.x*256 + threadIdx.x; i < n4; i += (size_t)gridDim.x*256) {
        float4 x = *(const float4*)(src + i*4);
        float hx = tobf(x.x), hy = tobf(x.y), hz = tobf(x.z), hw = tobf(x.w);
        *(uint2*)(dh + i*4) = make_uint2(pk(hx,hy), pk(hz,hw));
        *(uint2*)(dl + i*4) = make_uint2(pk(x.x-hx, x.y-hy), pk(x.z-hz, x.w-hw));
    }
}

// ---------------------------------------------------------------------------
// Projections (compensated bf16 mma), Lorentz epilogue, bf16 hi/lo outputs.
// ---------------------------------------------------------------------------
__global__ __launch_bounds__(256, 1) void proj_kernel(
    const float* __restrict__ bq, const float* __restrict__ sq,
    const float* __restrict__ bk, const float* __restrict__ sk,
    const float* __restrict__ bv, const float* __restrict__ sv)
{
    const int z = blockIdx.z;
    const float* bias = (z==0)?bq:(z==1)?bk:bv;
    const float* lsc  = (z==0)?sq:(z==1)?sk:sv;
    const __nv_bfloat16* Xhi = gXhi[z];
    const __nv_bfloat16* Xlo = gXlo[z];
    const __nv_bfloat16* Whi = gWhi[z];
    const __nv_bfloat16* Wlo = gWlo[z];

    extern __shared__ char smraw[];
    const unsigned sb = (smem_u32(smraw) + 1023u) & ~1023u;

    const int tid = threadIdx.x;
    const int w = tid >> 5, l = tid & 31;
    const int n0 = blockIdx.x * 128;
    const int m0 = blockIdx.y * 128;

    float cc[16][4];
#pragma unroll
    for (int i = 0; i < 16; i++)
#pragma unroll
        for (int j = 0; j < 4; j++) cc[i][j] = 0.f;

    const unsigned krow = (l & 7) + ((l & 16) >> 1);
    const unsigned kchalf = ((l >> 3) & 1) * 16;
    const unsigned qoff = (unsigned)(w * 16 + (l & 15)) * 128 + ((l >> 4) * 16);
    const int rr = tid >> 3, ch = tid & 7;

    auto issue = [&](int s, int kc) {
        unsigned base = sb + (unsigned)s * 65536u;
        const int k0 = kc * 64;
#pragma unroll
        for (int it = 0; it < 4; it++) {
            int r = rr + it * 32;
            unsigned sw = SWZ((unsigned)(r * 128 + ch * 16));
            cpa(base + sw,          Xhi + (size_t)(m0 + r) * Dz + k0 + ch * 8);
            cpa(base + 16384u + sw, Xlo + (size_t)(m0 + r) * Dz + k0 + ch * 8);
            cpa(base + 32768u + sw, Whi + (size_t)(n0 + r) * Dz + k0 + ch * 8);
            cpa(base + 49152u + sw, Wlo + (size_t)(n0 + r) * Dz + k0 + ch * 8);
        }
        CP_COMMIT();
    };

    issue(0, 0);
    for (int kc = 0; kc < 8; kc++) {
        __syncthreads();
        if (kc < 7) { issue((kc + 1) & 1, kc + 1); CP_WAIT(1); }
        else        { CP_WAIT(0); }
        __syncthreads();
        const unsigned base = sb + (unsigned)(kc & 1) * 65536u;

        unsigned ah[4][4], al[4][4];
#pragma unroll
        for (int c = 0; c < 4; c++) {
            unsigned sw = SWZ(qoff + c * 32);
            ldsm4(base + sw,          ah[c][0], ah[c][1], ah[c][2], ah[c][3]);
            ldsm4(base + 16384u + sw, al[c][0], al[c][1], al[c][2], al[c][3]);
        }
#pragma unroll
        for (int g = 0; g < 8; g++) {
            unsigned goff = (unsigned)(g * 16 + krow) * 128 + kchalf;
#pragma unroll
            for (int c = 0; c < 4; c++) {
                unsigned b0, b1, b2, b3, e0, e1, e2, e3;
                unsigned sw = SWZ(goff + c * 32);
                ldsm4(base + 32768u + sw, b0, b1, b2, b3);
                ldsm4(base + 49152u + sw, e0, e1, e2, e3);
                mma16816(cc[2*g],   ah[c], b0, b1);
                mma16816(cc[2*g+1], ah[c], b2, b3);
                mma16816(cc[2*g],   al[c], b0, b1);
                mma16816(cc[2*g+1], al[c], b2, b3);
                mma16816(cc[2*g],   ah[c], e0, e1);
                mma16816(cc[2*g+1], ah[c], e2, e3);
            }
        }
    }

    const float es = expf(lsc[0]);
    const int colq = (l & 3) * 2;
    const int r0 = m0 + w * 16 + (l >> 2);
    const int hbase = n0 >> 6;

#pragma unroll
    for (int t = 0; t < 16; t++) {
        float bv0 = bias[n0 + t*8 + colq];
        float bv1 = bias[n0 + t*8 + colq + 1];
        cc[t][0] += bv0; cc[t][1] += bv1;
        cc[t][2] += bv0; cc[t][3] += bv1;
    }

    __nv_bfloat16* outh = gPhi[z];
    __nv_bfloat16* outl = gPlo[z];

#pragma unroll
    for (int g2 = 0; g2 < 2; g2++) {
        float pp0 = 0.f, pp1 = 0.f;
#pragma unroll
        for (int tt = 0; tt < 8; tt++) {
            int t = g2 * 8 + tt;
            bool istime = (colq == 0) && (tt == 0);
            float y00 = cc[t][0], y01 = cc[t][1], y10 = cc[t][2], y11 = cc[t][3];
            pp0 += (istime ? 0.f : y00*y00) + y01*y01;
            pp1 += (istime ? 0.f : y10*y10) + y11*y11;
        }
        pp0 += __shfl_xor_sync(0xffffffffu, pp0, 1);
        pp0 += __shfl_xor_sync(0xffffffffu, pp0, 2);
        pp1 += __shfl_xor_sync(0xffffffffu, pp1, 1);
        pp1 += __shfl_xor_sync(0xffffffffu, pp1, 2);
        float t0 = 0.f, t1 = 0.f, f0 = 0.f, f1 = 0.f;
        if ((l & 3) == 0) {
            t0 = es / (1.f + expf(-cc[g2*8][0])) + 1.1f;
            t1 = es / (1.f + expf(-cc[g2*8][2])) + 1.1f;
            f0 = sqrtf((t0*t0 - 1.f) / fmaxf(pp0, 1e-8f));
            f1 = sqrtf((t1*t1 - 1.f) / fmaxf(pp1, 1e-8f));
        }
        int src = l & ~3;
        t0 = __shfl_sync(0xffffffffu, t0, src);
        t1 = __shfl_sync(0xffffffffu, t1, src);
        f0 = __shfl_sync(0xffffffffu, f0, src);
        f1 = __shfl_sync(0xffffffffu, f1, src);

        int h = hbase + g2;
        int bb0 = r0 >> 11, s0 = r0 & (Sz - 1);
        int r1 = r0 + 8;
        int bb1 = r1 >> 11, s1 = r1 & (Sz - 1);
        size_t o0 = ((size_t)((bb0*Hz + h)*Sz + s0)) * DPH;
        size_t o1 = ((size_t)((bb1*Hz + h)*Sz + s1)) * DPH;
#pragma unroll
        for (int tt = 0; tt < 8; tt++) {
            int t = g2 * 8 + tt;
            int lc = tt * 8 + colq;
            bool istime = (lc == 0);
            float v00 = istime ? ((z == 0) ? -t0 : t0) : cc[t][0] * f0;
            float v01 = cc[t][1] * f0;
            float v10 = istime ? ((z == 0) ? -t1 : t1) : cc[t][2] * f1;
            float v11 = cc[t][3] * f1;
            float h00 = tobf(v00), h01 = tobf(v01), h10 = tobf(v10), h11 = tobf(v11);
            *(unsigned*)(outh + o0 + lc) = pk(h00, h01);
            *(unsigned*)(outl + o0 + lc) = pk(v00 - h00, v01 - h01);
            *(unsigned*)(outh + o1 + lc) = pk(h10, h11);
            *(unsigned*)(outl + o1 + lc) = pk(v10 - h10, v11 - h11);
        }
    }
}

// ---------------------------------------------------------------------------
// Attention pass 1: l row-sums + ctx. No P writes. Double-buffered cp.async.
// ---------------------------------------------------------------------------
__global__ __launch_bounds__(256, 1) void attn_kernel(
    float* __restrict__ ctx, const float* __restrict__ scale_ptr)
{
    extern __shared__ char smraw[];
    const unsigned sb = (smem_u32(smraw) + 1023u) & ~1023u;

    const int blk = blockIdx.x;
    const int bh = blk & 15;
    const int qt = (NQT - 1) - (blk >> 4);
    const int q0 = qt * QT;
    const int b = bh >> 3, h = bh & 7;

    const int tid = threadIdx.x;
    const int w = tid >> 5, l = tid & 31;

    const float inv_as = 1.f / scale_ptr[0];
    const __nv_bfloat16* Qhi = gPhi[0] + (size_t)bh * Sz * DPH;
    const __nv_bfloat16* Qlo = gPlo[0] + (size_t)bh * Sz * DPH;
    const __nv_bfloat16* Khi = gPhi[1] + (size_t)bh * Sz * DPH;
    const __nv_bfloat16* Klo = gPlo[1] + (size_t)bh * Sz * DPH;
    const __nv_bfloat16* Vhi = gPhi[2] + (size_t)bh * Sz * DPH;
    const __nv_bfloat16* Vlo = gPlo[2] + (size_t)bh * Sz * DPH;

    const int rr = tid >> 3, chk = tid & 7;

    auto issue_kv = [&](int s, int kt) {
        unsigned base = sb + SM_KV + (unsigned)s * 65536u;
        const int k0 = kt * QT;
#pragma unroll
        for (int it = 0; it < 4; it++) {
            int r = rr + it * 32;
            unsigned sw = SWZ((unsigned)(r * 128 + chk * 16));
            const size_t go = (size_t)(k0 + r) * DPH + chk * 8;
            cpa(base + sw,          Khi + go);
            cpa(base + 16384u + sw, Klo + go);
            cpa(base + 32768u + sw, Vhi + go);
            cpa(base + 49152u + sw, Vlo + go);
        }
        CP_COMMIT();
    };

#pragma unroll
    for (int it = 0; it < 4; it++) {
        int r = rr + it * 32;
        unsigned sw = SWZ((unsigned)(r * 128 + chk * 16));
        cpa(sb + SM_QHI + sw, Qhi + (size_t)(q0 + r) * DPH + chk * 8);
        cpa(sb + SM_QLO + sw, Qlo + (size_t)(q0 + r) * DPH + chk * 8);
    }
    CP_COMMIT();
    issue_kv(0, 0);
    CP_WAIT(0);
    __syncthreads();

    unsigned qh[4][4], ql[4][4];
    {
        unsigned qoff = (unsigned)(w * 16 + (l & 15)) * 128 + ((l >> 4) * 16);
#pragma unroll
        for (int c = 0; c < 4; c++) {
            unsigned sw = SWZ(qoff + c * 32);
            ldsm4(sb + SM_QHI + sw, qh[c][0], qh[c][1], qh[c][2], qh[c][3]);
            ldsm4(sb + SM_QLO + sw, ql[c][0], ql[c][1], ql[c][2], ql[c][3]);
        }
    }

    const unsigned krow = (l & 7) + ((l & 16) >> 1);
    const unsigned kchalf = ((l >> 3) & 1) * 16;
    const unsigned vt = l >> 3;
    const unsigned vrow = (l & 7) + ((vt & 1) << 3);
    const unsigned vd8 = (vt >> 1) * 16;

    float cc[8][4];
#pragma unroll
    for (int i = 0; i < 8; i++)
#pragma unroll
        for (int j = 0; j < 4; j++) cc[i][j] = 0.f;
    float lsum0 = 0.f, lsum1 = 0.f;

    const int row0 = w * 16 + (l >> 2);
    const int gq0 = q0 + row0, gq1 = gq0 + 8;
    const int colq = (l & 3) * 2;

    for (int kt = 0; kt <= qt; ++kt) {
        const int k0 = kt * QT;
        if (kt < qt) { issue_kv((kt + 1) & 1, kt + 1); CP_WAIT(1); }
        else         { CP_WAIT(0); }
        __syncthreads();
        const unsigned kb = sb + SM_KV + (unsigned)(kt & 1) * 65536u;

        float sc[16][4];
#pragma unroll
        for (int i = 0; i < 16; i++)
#pragma unroll
            for (int j = 0; j < 4; j++) sc[i][j] = 0.f;
#pragma unroll
        for (int g = 0; g < 8; g++) {
            unsigned goff = (unsigned)(g * 16 + krow) * 128 + kchalf;
#pragma unroll
            for (int c = 0; c < 4; c++) {
                unsigned b0, b1, b2, b3, e0, e1, e2, e3;
                unsigned sw = SWZ(goff + c * 32);
                ldsm4(kb + sw,          b0, b1, b2, b3);
                ldsm4(kb + 16384u + sw, e0, e1, e2, e3);
                mma16816(sc[2*g],   qh[c], b0, b1);
                mma16816(sc[2*g+1], qh[c], b2, b3);
                mma16816(sc[2*g],   ql[c], b0, b1);
                mma16816(sc[2*g+1], ql[c], b2, b3);
                mma16816(sc[2*g],   qh[c], e0, e1);
                mma16816(sc[2*g+1], qh[c], e2, e3);
            }
        }

        const bool diag = (kt == qt);
#pragma unroll
        for (int t = 0; t < 16; t++) {
            int gk = k0 + t * 8 + colq;
            float v0 = __expf((2.f * sc[t][0] + 2.f) * inv_as);
            float v1 = __expf((2.f * sc[t][1] + 2.f) * inv_as);
            float v2 = __expf((2.f * sc[t][2] + 2.f) * inv_as);
            float v3 = __expf((2.f * sc[t][3] + 2.f) * inv_as);
            if (diag) {
                if (gk > gq0)     v0 = 0.f;
                if (gk + 1 > gq0) v1 = 0.f;
                if (gk > gq1)     v2 = 0.f;
                if (gk + 1 > gq1) v3 = 0.f;
            }
            sc[t][0] = v0; sc[t][1] = v1; sc[t][2] = v2; sc[t][3] = v3;
            lsum0 += v0 + v1;
            lsum1 += v2 + v3;
        }

#pragma unroll
        for (int kc = 0; kc < 8; kc++) {
            unsigned ah[4], al[4];
            {
                float x0 = sc[2*kc][0], x1 = sc[2*kc][1], x2 = sc[2*kc][2], x3 = sc[2*kc][3];
                float y0 = sc[2*kc+1][0], y1 = sc[2*kc+1][1], y2 = sc[2*kc+1][2], y3 = sc[2*kc+1][3];
                float hx0 = tobf(x0), hx1 = tobf(x1), hx2 = tobf(x2), hx3 = tobf(x3);
                float hy0 = tobf(y0), hy1 = tobf(y1), hy2 = tobf(y2), hy3 = tobf(y3);
                ah[0] = pk(hx0, hx1); ah[1] = pk(hx2, hx3);
                ah[2] = pk(hy0, hy1); ah[3] = pk(hy2, hy3);
                al[0] = pk(x0 - hx0, x1 - hx1); al[1] = pk(x2 - hx2, x3 - hx3);
                al[2] = pk(y0 - hy0, y1 - hy1); al[3] = pk(y2 - hy2, y3 - hy3);
            }
            unsigned koff = (unsigned)(kc * 16 + vrow) * 128 + vd8;
#pragma unroll
            for (int g = 0; g < 4; g++) {
                unsigned b0, b1, b2, b3, e0, e1, e2, e3;
                unsigned sw = SWZ(koff + g * 32);
                ldsm4t(kb + 32768u + sw, b0, b1, b2, b3);
                ldsm4t(kb + 49152u + sw, e0, e1, e2, e3);
                mma16816(cc[2*g],   ah, b0, b1);
                mma16816(cc[2*g+1], ah, b2, b3);
                mma16816(cc[2*g],   al, b0, b1);
                mma16816(cc[2*g+1], al, b2, b3);
                mma16816(cc[2*g],   ah, e0, e1);
                mma16816(cc[2*g+1], ah, e2, e3);
            }
        }
        __syncthreads();
    }

    lsum0 += __shfl_xor_sync(0xffffffffu, lsum0, 1);
    lsum0 += __shfl_xor_sync(0xffffffffu, lsum0, 2);
    lsum1 += __shfl_xor_sync(0xffffffffu, lsum1, 1);
    lsum1 += __shfl_xor_sync(0xffffffffu, lsum1, 2);
    if ((l & 3) == 0) {
        g_l[bh*Sz + gq0] = lsum0;
        g_l[bh*Sz + gq1] = lsum1;
    }

    float pp0 = 0.f, pp1 = 0.f;
#pragma unroll
    for (int t = 0; t < 8; t++) {
        float a0 = cc[t][0], a1 = cc[t][1], a2 = cc[t][2], a3 = cc[t][3];
        float s0 = (t == 0 && (l & 3) == 0) ? -a0*a0 : a0*a0;
        float s2 = (t == 0 && (l & 3) == 0) ? -a2*a2 : a2*a2;
        pp0 += s0 + a1*a1;
        pp1 += s2 + a3*a3;
    }
    pp0 += __shfl_xor_sync(0xffffffffu, pp0, 1);
    pp0 += __shfl_xor_sync(0xffffffffu, pp0, 2);
    pp1 += __shfl_xor_sync(0xffffffffu, pp1, 1);
    pp1 += __shfl_xor_sync(0xffffffffu, pp1, 2);
    float inv0 = rsqrtf(fmaxf(fabsf(pp0), 1e-8f));
    float inv1 = rsqrtf(fmaxf(fabsf(pp1), 1e-8f));
    float* c0p = ctx + ((size_t)((b*Sz + gq0)*Hz + h)) * DPH + colq;
    float* c1p = ctx + ((size_t)((b*Sz + gq1)*Hz + h)) * DPH + colq;
#pragma unroll
    for (int t = 0; t < 8; t++) {
        *(float2*)(c0p + t*8) = make_float2(cc[t][0]*inv0, cc[t][1]*inv0);
        *(float2*)(c1p + t*8) = make_float2(cc[t][2]*inv1, cc[t][3]*inv1);
    }
}

// ---------------------------------------------------------------------------
// Attention pass 2: recompute S, write normalized attn (incl. zero upper tri).
// Single-stage K buffer + 2 CTAs/SM: occupancy covers the load latency.
// ---------------------------------------------------------------------------
__global__ __launch_bounds__(256, 2) void pass2_kernel(
    float* __restrict__ attn, const float* __restrict__ scale_ptr)
{
    extern __shared__ char smraw[];
    const unsigned sb = (smem_u32(smraw) + 1023u) & ~1023u;

    const int blk = blockIdx.x;
    const int bh = blk & 15;
    const int qt = (NQT - 1) - (blk >> 4);
    const int q0 = qt * QT;

    const int tid = threadIdx.x;
    const int w = tid >> 5, l = tid & 31;

    const float inv_as = 1.f / scale_ptr[0];
    const __nv_bfloat16* Qhi = gPhi[0] + (size_t)bh * Sz * DPH;
    const __nv_bfloat16* Qlo = gPlo[0] + (size_t)bh * Sz * DPH;
    const __nv_bfloat16* Khi = gPhi[1] + (size_t)bh * Sz * DPH;
    const __nv_bfloat16* Klo = gPlo[1] + (size_t)bh * Sz * DPH;
    float* arow = attn + (size_t)bh * Sz * Sz;

    const int rr = tid >> 3, chk = tid & 7;

    auto issue_k = [&](int kt) {
        unsigned base = sb + 32768u;
        const int k0 = kt * QT;
#pragma unroll
        for (int it = 0; it < 4; it++) {
            int r = rr + it * 32;
            unsigned sw = SWZ((unsigned)(r * 128 + chk * 16));
            const size_t go = (size_t)(k0 + r) * DPH + chk * 8;
            cpa(base + sw,          Khi + go);
            cpa(base + 16384u + sw, Klo + go);
        }
        CP_COMMIT();
    };

#pragma unroll
    for (int it = 0; it < 4; it++) {
        int r = rr + it * 32;
        unsigned sw = SWZ((unsigned)(r * 128 + chk * 16));
        cpa(sb + sw,          Qhi + (size_t)(q0 + r) * DPH + chk * 8);
        cpa(sb + 16384u + sw, Qlo + (size_t)(q0 + r) * DPH + chk * 8);
    }
    CP_COMMIT();
    issue_k(0);
    CP_WAIT(0);
    __syncthreads();

    unsigned qh[4][4], ql[4][4];
    {
        unsigned qoff = (unsigned)(w * 16 + (l & 15)) * 128 + ((l >> 4) * 16);
#pragma unroll
        for (int c = 0; c < 4; c++) {
            unsigned sw = SWZ(qoff + c * 32);
            ldsm4(sb + sw,          qh[c][0], qh[c][1], qh[c][2], qh[c][3]);
            ldsm4(sb + 16384u + sw, ql[c][0], ql[c][1], ql[c][2], ql[c][3]);
        }
    }

    const unsigned krow = (l & 7) + ((l & 16) >> 1);
    const unsigned kchalf = ((l >> 3) & 1) * 16;

    const int row0 = w * 16 + (l >> 2);
    const int gq0 = q0 + row0, gq1 = gq0 + 8;
    const int colq = (l & 3) * 2;
    const float il0 = 1.f / g_l[bh*Sz + gq0];
    const float il1 = 1.f / g_l[bh*Sz + gq1];

    for (int kt = 0; kt <= qt; ++kt) {
        const int k0 = kt * QT;
        const unsigned kb = sb + 32768u;

        float sc[16][4];
#pragma unroll
        for (int i = 0; i < 16; i++)
#pragma unroll
            for (int j = 0; j < 4; j++) sc[i][j] = 0.f;
#pragma unroll
        for (int g = 0; g < 8; g++) {
            unsigned goff = (unsigned)(g * 16 + krow) * 128 + kchalf;
#pragma unroll
            for (int c = 0; c < 4; c++) {
                unsigned b0, b1, b2, b3, e0, e1, e2, e3;
                unsigned sw = SWZ(goff + c * 32);
                ldsm4(kb + sw,          b0, b1, b2, b3);
                ldsm4(kb + 16384u + sw, e0, e1, e2, e3);
                mma16816(sc[2*g],   qh[c], b0, b1);
                mma16816(sc[2*g+1], qh[c], b2, b3);
                mma16816(sc[2*g],   ql[c], b0, b1);
                mma16816(sc[2*g+1], ql[c], b2, b3);
                mma16816(sc[2*g],   qh[c], e0, e1);
                mma16816(sc[2*g+1], qh[c], e2, e3);
            }
        }

        // next K tile: all warps done reading, start the single-stage reload
        __syncthreads();
        if (kt < qt) issue_k(kt + 1);

        const bool diag = (kt == qt);
        float* p0 = arow + (size_t)gq0 * Sz + k0 + colq;
        float* p1 = arow + (size_t)gq1 * Sz + k0 + colq;
#pragma unroll
        for (int t = 0; t < 16; t++) {
            int gk = k0 + t * 8 + colq;
            float v0 = __expf((2.f * sc[t][0] + 2.f) * inv_as) * il0;
            float v1 = __expf((2.f * sc[t][1] + 2.f) * inv_as) * il0;
            float v2 = __expf((2.f * sc[t][2] + 2.f) * inv_as) * il1;
            float v3 = __expf((2.f * sc[t][3] + 2.f) * inv_as) * il1;
            if (diag) {
                if (gk > gq0)     v0 = 0.f;
                if (gk + 1 > gq0) v1 = 0.f;
                if (gk > gq1)     v2 = 0.f;
                if (gk + 1 > gq1) v3 = 0.f;
            }
            *(float2*)(p0 + t*8) = make_float2(v0, v1);
            *(float2*)(p1 + t*8) = make_float2(v2, v3);
        }

        if (kt < qt) {
            CP_WAIT(0);
            __syncthreads();
        }
    }

    // zero the strict upper region (whole tiles right of the diagonal tile)
    const int z0 = (qt + 1) * QT;
    const int nz4 = (Sz - z0) >> 2;
    if (nz4 > 0) {
        const float4 zero = make_float4(0.f, 0.f, 0.f, 0.f);
        for (int idx = tid; idx < 128 * nz4; idx += 256) {
            int r = idx / nz4, c = idx % nz4;
            *(float4*)(arow + (size_t)(q0 + r) * Sz + z0 + c * 4) = zero;
        }
    }
}

extern "C" void kernel_launch(void* const* d_in, const int* in_sizes, int n_in,
                              void* d_out, int out_size)
{
    const float* key   = (const float*)d_in[0];
    const float* value = (const float*)d_in[1];
    const float* query = (const float*)d_in[2];
    const float* Wq = (const float*)d_in[4];
    const float* bq = (const float*)d_in[5];
    const float* sq = (const float*)d_in[6];
    const float* Wk = (const float*)d_in[7];
    const float* bk = (const float*)d_in[8];
    const float* sk = (const float*)d_in[9];
    const float* Wv = (const float*)d_in[10];
    const float* bv = (const float*)d_in[11];
    const float* sv = (const float*)d_in[12];
    const float* att_scale = (const float*)d_in[13];

    float* ctx  = (float*)d_out;
    float* attn = ctx + (size_t)Bz * Sz * Dz;

    dim3 gs(512, 6);
    split_kernel<<<gs, 256>>>(query, key, value, Wq, Wk, Wv);

    cudaFuncSetAttribute(proj_kernel, cudaFuncAttributeMaxDynamicSharedMemorySize, SMEM_PROJ);
    dim3 gp(Dz / 128, Mrows / 128, 3);
    proj_kernel<<<gp, 256, SMEM_PROJ>>>(bq, sq, bk, sk, bv, sv);

    cudaFuncSetAttribute(attn_kernel, cudaFuncAttributeMaxDynamicSharedMemorySize, SMEM_ATTN);
    attn_kernel<<<BHn * NQT, 256, SMEM_ATTN>>>(ctx, att_scale);

    cudaFuncSetAttribute(pass2_kernel, cudaFuncAttributeMaxDynamicSharedMemorySize, SMEM_P2);
    pass2_kernel<<<BHn * NQT, 256, SMEM_P2>>>(attn, att_scale);
}

// round 17
// speedup vs baseline: 1.0563x; 1.0563x over previous
#include <cuda_runtime.h>
#include <cuda_bf16.h>
#include <math.h>

#define Bz 2
#define Sz 2048
#define Dz 512
#define Hz 8
#define DPH 64
#define BHn (Bz*Hz)
#define Mrows (Bz*Sz)
#define QT 128
#define NQT (Sz/QT)
#define NX ((size_t)Mrows*Dz)
#define NW ((size_t)Dz*Dz)

__device__ __nv_bfloat16 gXhi[3][NX];
__device__ __nv_bfloat16 gXlo[3][NX];
__device__ __nv_bfloat16 gWhi[3][NW];
__device__ __nv_bfloat16 gWlo[3][NW];
__device__ __nv_bfloat16 gPhi[3][(size_t)BHn*Sz*DPH];
__device__ __nv_bfloat16 gPlo[3][(size_t)BHn*Sz*DPH];
__device__ float g_l[BHn*Sz];

// ===================== helpers =====================
__device__ __forceinline__ unsigned smem_u32(const void* p) {
    unsigned a;
    asm("{ .reg .u64 t; cvta.to.shared.u64 t, %1; cvt.u32.u64 %0, t; }" : "=r"(a) : "l"(p));
    return a;
}
#define SWZ(x) ((x) ^ (((x) >> 3) & 0x70))
__device__ __forceinline__ float tobf(float x) { return __bfloat162float(__float2bfloat16_rn(x)); }
__device__ __forceinline__ unsigned pk(float a, float b) {
    __nv_bfloat162 t = __floats2bfloat162_rn(a, b);
    return *(unsigned*)&t;
}
__device__ __forceinline__ void ldsm4(unsigned addr, unsigned& r0, unsigned& r1, unsigned& r2, unsigned& r3) {
    asm volatile("ldmatrix.sync.aligned.m8n8.x4.shared.b16 {%0,%1,%2,%3}, [%4];"
        : "=r"(r0), "=r"(r1), "=r"(r2), "=r"(r3) : "r"(addr));
}
__device__ __forceinline__ void ldsm4t(unsigned addr, unsigned& r0, unsigned& r1, unsigned& r2, unsigned& r3) {
    asm volatile("ldmatrix.sync.aligned.m8n8.x4.trans.shared.b16 {%0,%1,%2,%3}, [%4];"
        : "=r"(r0), "=r"(r1), "=r"(r2), "=r"(r3) : "r"(addr));
}
__device__ __forceinline__ void mma16816(float* c, const unsigned* a, unsigned b0, unsigned b1) {
    asm volatile("mma.sync.aligned.m16n8k16.row.col.f32.bf16.bf16.f32 "
        "{%0,%1,%2,%3},{%4,%5,%6,%7},{%8,%9},{%0,%1,%2,%3};"
        : "+f"(c[0]), "+f"(c[1]), "+f"(c[2]), "+f"(c[3])
        : "r"(a[0]), "r"(a[1]), "r"(a[2]), "r"(a[3]), "r"(b0), "r"(b1));
}
__device__ __forceinline__ void cpa(unsigned dst, const void* src) {
    asm volatile("cp.async.cg.shared.global [%0], [%1], 16;" :: "r"(dst), "l"(src));
}
#define CP_COMMIT() asm volatile("cp.async.commit_group;" ::: "memory")
#define CP_WAIT(n)  asm volatile("cp.async.wait_group %0;" :: "n"(n) : "memory")

// attn smem: Q 32KB + 2 stages x 64KB
#define SM_QHI 0u
#define SM_QLO 16384u
#define SM_KV  32768u
#define SMEM_ATTN (32768 + 2*65536 + 1024)
// pass2 smem: Q 32KB + 2 stages x 32KB (KHI,KLO)
#define SMEM_P2 (32768 + 2*32768 + 1024)
// proj smem: 2 stages x 64KB
#define SMEM_PROJ (131072 + 1024)

// ---------------------------------------------------------------------------
__global__ __launch_bounds__(256) void split_kernel(
    const float* __restrict__ q, const float* __restrict__ k, const float* __restrict__ v,
    const float* __restrict__ wq, const float* __restrict__ wk, const float* __restrict__ wv)
{
    const int z = blockIdx.y;
    const float* src = (z==0)?q:(z==1)?k:(z==2)?v:(z==3)?wq:(z==4)?wk:wv;
    __nv_bfloat16* dh; __nv_bfloat16* dl; size_t n4;
    if (z < 3) { dh = gXhi[z]; dl = gXlo[z]; n4 = NX/4; }
    else       { dh = gWhi[z-3]; dl = gWlo[z-3]; n4 = NW/4; }
    for (size_t i = blockIdx.x*256 + threadIdx.x; i < n4; i += (size_t)gridDim.x*256) {
        float4 x = *(const float4*)(src + i*4);
        float hx = tobf(x.x), hy = tobf(x.y), hz = tobf(x.z), hw = tobf(x.w);
        *(uint2*)(dh + i*4) = make_uint2(pk(hx,hy), pk(hz,hw));
        *(uint2*)(dl + i*4) = make_uint2(pk(x.x-hx, x.y-hy), pk(x.z-hz, x.w-hw));
    }
}

// ---------------------------------------------------------------------------
// Projections (compensated bf16 mma), Lorentz epilogue, bf16 hi/lo outputs.
// ---------------------------------------------------------------------------
__global__ __launch_bounds__(256, 1) void proj_kernel(
    const float* __restrict__ bq, const float* __restrict__ sq,
    const float* __restrict__ bk, const float* __restrict__ sk,
    const float* __restrict__ bv, const float* __restrict__ sv)
{
    const int z = blockIdx.z;
    const float* bias = (z==0)?bq:(z==1)?bk:bv;
    const float* lsc  = (z==0)?sq:(z==1)?sk:sv;
    const __nv_bfloat16* Xhi = gXhi[z];
    const __nv_bfloat16* Xlo = gXlo[z];
    const __nv_bfloat16* Whi = gWhi[z];
    const __nv_bfloat16* Wlo = gWlo[z];

    extern __shared__ char smraw[];
    const unsigned sb = (smem_u32(smraw) + 1023u) & ~1023u;

    const int tid = threadIdx.x;
    const int w = tid >> 5, l = tid & 31;
    const int n0 = blockIdx.x * 128;
    const int m0 = blockIdx.y * 128;

    float cc[16][4];
#pragma unroll
    for (int i = 0; i < 16; i++)
#pragma unroll
        for (int j = 0; j < 4; j++) cc[i][j] = 0.f;

    const unsigned krow = (l & 7) + ((l & 16) >> 1);
    const unsigned kchalf = ((l >> 3) & 1) * 16;
    const unsigned qoff = (unsigned)(w * 16 + (l & 15)) * 128 + ((l >> 4) * 16);
    const int rr = tid >> 3, ch = tid & 7;

    auto issue = [&](int s, int kc) {
        unsigned base = sb + (unsigned)s * 65536u;
        const int k0 = kc * 64;
#pragma unroll
        for (int it = 0; it < 4; it++) {
            int r = rr + it * 32;
            unsigned sw = SWZ((unsigned)(r * 128 + ch * 16));
            cpa(base + sw,          Xhi + (size_t)(m0 + r) * Dz + k0 + ch * 8);
            cpa(base + 16384u + sw, Xlo + (size_t)(m0 + r) * Dz + k0 + ch * 8);
            cpa(base + 32768u + sw, Whi + (size_t)(n0 + r) * Dz + k0 + ch * 8);
            cpa(base + 49152u + sw, Wlo + (size_t)(n0 + r) * Dz + k0 + ch * 8);
        }
        CP_COMMIT();
    };

    issue(0, 0);
    for (int kc = 0; kc < 8; kc++) {
        __syncthreads();
        if (kc < 7) { issue((kc + 1) & 1, kc + 1); CP_WAIT(1); }
        else        { CP_WAIT(0); }
        __syncthreads();
        const unsigned base = sb + (unsigned)(kc & 1) * 65536u;

        unsigned ah[4][4], al[4][4];
#pragma unroll
        for (int c = 0; c < 4; c++) {
            unsigned sw = SWZ(qoff + c * 32);
            ldsm4(base + sw,          ah[c][0], ah[c][1], ah[c][2], ah[c][3]);
            ldsm4(base + 16384u + sw, al[c][0], al[c][1], al[c][2], al[c][3]);
        }
#pragma unroll
        for (int g = 0; g < 8; g++) {
            unsigned goff = (unsigned)(g * 16 + krow) * 128 + kchalf;
#pragma unroll
            for (int c = 0; c < 4; c++) {
                unsigned b0, b1, b2, b3, e0, e1, e2, e3;
                unsigned sw = SWZ(goff + c * 32);
                ldsm4(base + 32768u + sw, b0, b1, b2, b3);
                ldsm4(base + 49152u + sw, e0, e1, e2, e3);
                mma16816(cc[2*g],   ah[c], b0, b1);
                mma16816(cc[2*g+1], ah[c], b2, b3);
                mma16816(cc[2*g],   al[c], b0, b1);
                mma16816(cc[2*g+1], al[c], b2, b3);
                mma16816(cc[2*g],   ah[c], e0, e1);
                mma16816(cc[2*g+1], ah[c], e2, e3);
            }
        }
    }

    const float es = expf(lsc[0]);
    const int colq = (l & 3) * 2;
    const int r0 = m0 + w * 16 + (l >> 2);
    const int hbase = n0 >> 6;

#pragma unroll
    for (int t = 0; t < 16; t++) {
        float bv0 = bias[n0 + t*8 + colq];
        float bv1 = bias[n0 + t*8 + colq + 1];
        cc[t][0] += bv0; cc[t][1] += bv1;
        cc[t][2] += bv0; cc[t][3] += bv1;
    }

    __nv_bfloat16* outh = gPhi[z];
    __nv_bfloat16* outl = gPlo[z];

#pragma unroll
    for (int g2 = 0; g2 < 2; g2++) {
        float pp0 = 0.f, pp1 = 0.f;
#pragma unroll
        for (int tt = 0; tt < 8; tt++) {
            int t = g2 * 8 + tt;
            bool istime = (colq == 0) && (tt == 0);
            float y00 = cc[t][0], y01 = cc[t][1], y10 = cc[t][2], y11 = cc[t][3];
            pp0 += (istime ? 0.f : y00*y00) + y01*y01;
            pp1 += (istime ? 0.f : y10*y10) + y11*y11;
        }
        pp0 += __shfl_xor_sync(0xffffffffu, pp0, 1);
        pp0 += __shfl_xor_sync(0xffffffffu, pp0, 2);
        pp1 += __shfl_xor_sync(0xffffffffu, pp1, 1);
        pp1 += __shfl_xor_sync(0xffffffffu, pp1, 2);
        float t0 = 0.f, t1 = 0.f, f0 = 0.f, f1 = 0.f;
        if ((l & 3) == 0) {
            t0 = es / (1.f + expf(-cc[g2*8][0])) + 1.1f;
            t1 = es / (1.f + expf(-cc[g2*8][2])) + 1.1f;
            f0 = sqrtf((t0*t0 - 1.f) / fmaxf(pp0, 1e-8f));
            f1 = sqrtf((t1*t1 - 1.f) / fmaxf(pp1, 1e-8f));
        }
        int src = l & ~3;
        t0 = __shfl_sync(0xffffffffu, t0, src);
        t1 = __shfl_sync(0xffffffffu, t1, src);
        f0 = __shfl_sync(0xffffffffu, f0, src);
        f1 = __shfl_sync(0xffffffffu, f1, src);

        int h = hbase + g2;
        int bb0 = r0 >> 11, s0 = r0 & (Sz - 1);
        int r1 = r0 + 8;
        int bb1 = r1 >> 11, s1 = r1 & (Sz - 1);
        size_t o0 = ((size_t)((bb0*Hz + h)*Sz + s0)) * DPH;
        size_t o1 = ((size_t)((bb1*Hz + h)*Sz + s1)) * DPH;
#pragma unroll
        for (int tt = 0; tt < 8; tt++) {
            int t = g2 * 8 + tt;
            int lc = tt * 8 + colq;
            bool istime = (lc == 0);
            float v00 = istime ? ((z == 0) ? -t0 : t0) : cc[t][0] * f0;
            float v01 = cc[t][1] * f0;
            float v10 = istime ? ((z == 0) ? -t1 : t1) : cc[t][2] * f1;
            float v11 = cc[t][3] * f1;
            float h00 = tobf(v00), h01 = tobf(v01), h10 = tobf(v10), h11 = tobf(v11);
            *(unsigned*)(outh + o0 + lc) = pk(h00, h01);
            *(unsigned*)(outl + o0 + lc) = pk(v00 - h00, v01 - h01);
            *(unsigned*)(outh + o1 + lc) = pk(h10, h11);
            *(unsigned*)(outl + o1 + lc) = pk(v10 - h10, v11 - h11);
        }
    }
}

// ---------------------------------------------------------------------------
// Attention pass 1: l row-sums + ctx. No P writes. Double-buffered cp.async.
// ---------------------------------------------------------------------------
__global__ __launch_bounds__(256, 1) void attn_kernel(
    float* __restrict__ ctx, const float* __restrict__ scale_ptr)
{
    extern __shared__ char smraw[];
    const unsigned sb = (smem_u32(smraw) + 1023u) & ~1023u;

    const int blk = blockIdx.x;
    const int bh = blk & 15;
    const int qt = (NQT - 1) - (blk >> 4);
    const int q0 = qt * QT;
    const int b = bh >> 3, h = bh & 7;

    const int tid = threadIdx.x;
    const int w = tid >> 5, l = tid & 31;

    const float inv_as = 1.f / scale_ptr[0];
    const __nv_bfloat16* Qhi = gPhi[0] + (size_t)bh * Sz * DPH;
    const __nv_bfloat16* Qlo = gPlo[0] + (size_t)bh * Sz * DPH;
    const __nv_bfloat16* Khi = gPhi[1] + (size_t)bh * Sz * DPH;
    const __nv_bfloat16* Klo = gPlo[1] + (size_t)bh * Sz * DPH;
    const __nv_bfloat16* Vhi = gPhi[2] + (size_t)bh * Sz * DPH;
    const __nv_bfloat16* Vlo = gPlo[2] + (size_t)bh * Sz * DPH;

    const int rr = tid >> 3, chk = tid & 7;

    auto issue_kv = [&](int s, int kt) {
        unsigned base = sb + SM_KV + (unsigned)s * 65536u;
        const int k0 = kt * QT;
#pragma unroll
        for (int it = 0; it < 4; it++) {
            int r = rr + it * 32;
            unsigned sw = SWZ((unsigned)(r * 128 + chk * 16));
            const size_t go = (size_t)(k0 + r) * DPH + chk * 8;
            cpa(base + sw,          Khi + go);
            cpa(base + 16384u + sw, Klo + go);
            cpa(base + 32768u + sw, Vhi + go);
            cpa(base + 49152u + sw, Vlo + go);
        }
        CP_COMMIT();
    };

#pragma unroll
    for (int it = 0; it < 4; it++) {
        int r = rr + it * 32;
        unsigned sw = SWZ((unsigned)(r * 128 + chk * 16));
        cpa(sb + SM_QHI + sw, Qhi + (size_t)(q0 + r) * DPH + chk * 8);
        cpa(sb + SM_QLO + sw, Qlo + (size_t)(q0 + r) * DPH + chk * 8);
    }
    CP_COMMIT();
    issue_kv(0, 0);
    CP_WAIT(0);
    __syncthreads();

    unsigned qh[4][4], ql[4][4];
    {
        unsigned qoff = (unsigned)(w * 16 + (l & 15)) * 128 + ((l >> 4) * 16);
#pragma unroll
        for (int c = 0; c < 4; c++) {
            unsigned sw = SWZ(qoff + c * 32);
            ldsm4(sb + SM_QHI + sw, qh[c][0], qh[c][1], qh[c][2], qh[c][3]);
            ldsm4(sb + SM_QLO + sw, ql[c][0], ql[c][1], ql[c][2], ql[c][3]);
        }
    }

    const unsigned krow = (l & 7) + ((l & 16) >> 1);
    const unsigned kchalf = ((l >> 3) & 1) * 16;
    const unsigned vt = l >> 3;
    const unsigned vrow = (l & 7) + ((vt & 1) << 3);
    const unsigned vd8 = (vt >> 1) * 16;

    float cc[8][4];
#pragma unroll
    for (int i = 0; i < 8; i++)
#pragma unroll
        for (int j = 0; j < 4; j++) cc[i][j] = 0.f;
    float lsum0 = 0.f, lsum1 = 0.f;

    const int row0 = w * 16 + (l >> 2);
    const int gq0 = q0 + row0, gq1 = gq0 + 8;
    const int colq = (l & 3) * 2;

    for (int kt = 0; kt <= qt; ++kt) {
        const int k0 = kt * QT;
        if (kt < qt) { issue_kv((kt + 1) & 1, kt + 1); CP_WAIT(1); }
        else         { CP_WAIT(0); }
        __syncthreads();
        const unsigned kb = sb + SM_KV + (unsigned)(kt & 1) * 65536u;

        float sc[16][4];
#pragma unroll
        for (int i = 0; i < 16; i++)
#pragma unroll
            for (int j = 0; j < 4; j++) sc[i][j] = 0.f;
#pragma unroll
        for (int g = 0; g < 8; g++) {
            unsigned goff = (unsigned)(g * 16 + krow) * 128 + kchalf;
#pragma unroll
            for (int c = 0; c < 4; c++) {
                unsigned b0, b1, b2, b3, e0, e1, e2, e3;
                unsigned sw = SWZ(goff + c * 32);
                ldsm4(kb + sw,          b0, b1, b2, b3);
                ldsm4(kb + 16384u + sw, e0, e1, e2, e3);
                mma16816(sc[2*g],   qh[c], b0, b1);
                mma16816(sc[2*g+1], qh[c], b2, b3);
                mma16816(sc[2*g],   ql[c], b0, b1);
                mma16816(sc[2*g+1], ql[c], b2, b3);
                mma16816(sc[2*g],   qh[c], e0, e1);
                mma16816(sc[2*g+1], qh[c], e2, e3);
            }
        }

        const bool diag = (kt == qt);
#pragma unroll
        for (int t = 0; t < 16; t++) {
            int gk = k0 + t * 8 + colq;
            float v0 = __expf((2.f * sc[t][0] + 2.f) * inv_as);
            float v1 = __expf((2.f * sc[t][1] + 2.f) * inv_as);
            float v2 = __expf((2.f * sc[t][2] + 2.f) * inv_as);
            float v3 = __expf((2.f * sc[t][3] + 2.f) * inv_as);
            if (diag) {
                if (gk > gq0)     v0 = 0.f;
                if (gk + 1 > gq0) v1 = 0.f;
                if (gk > gq1)     v2 = 0.f;
                if (gk + 1 > gq1) v3 = 0.f;
            }
            sc[t][0] = v0; sc[t][1] = v1; sc[t][2] = v2; sc[t][3] = v3;
            lsum0 += v0 + v1;
            lsum1 += v2 + v3;
        }

#pragma unroll
        for (int kc = 0; kc < 8; kc++) {
            unsigned ah[4], al[4];
            {
                float x0 = sc[2*kc][0], x1 = sc[2*kc][1], x2 = sc[2*kc][2], x3 = sc[2*kc][3];
                float y0 = sc[2*kc+1][0], y1 = sc[2*kc+1][1], y2 = sc[2*kc+1][2], y3 = sc[2*kc+1][3];
                float hx0 = tobf(x0), hx1 = tobf(x1), hx2 = tobf(x2), hx3 = tobf(x3);
                float hy0 = tobf(y0), hy1 = tobf(y1), hy2 = tobf(y2), hy3 = tobf(y3);
                ah[0] = pk(hx0, hx1); ah[1] = pk(hx2, hx3);
                ah[2] = pk(hy0, hy1); ah[3] = pk(hy2, hy3);
                al[0] = pk(x0 - hx0, x1 - hx1); al[1] = pk(x2 - hx2, x3 - hx3);
                al[2] = pk(y0 - hy0, y1 - hy1); al[3] = pk(y2 - hy2, y3 - hy3);
            }
            unsigned koff = (unsigned)(kc * 16 + vrow) * 128 + vd8;
#pragma unroll
            for (int g = 0; g < 4; g++) {
                unsigned b0, b1, b2, b3, e0, e1, e2, e3;
                unsigned sw = SWZ(koff + g * 32);
                ldsm4t(kb + 32768u + sw, b0, b1, b2, b3);
                ldsm4t(kb + 49152u + sw, e0, e1, e2, e3);
                mma16816(cc[2*g],   ah, b0, b1);
                mma16816(cc[2*g+1], ah, b2, b3);
                mma16816(cc[2*g],   al, b0, b1);
                mma16816(cc[2*g+1], al, b2, b3);
                mma16816(cc[2*g],   ah, e0, e1);
                mma16816(cc[2*g+1], ah, e2, e3);
            }
        }
        __syncthreads();
    }

    lsum0 += __shfl_xor_sync(0xffffffffu, lsum0, 1);
    lsum0 += __shfl_xor_sync(0xffffffffu, lsum0, 2);
    lsum1 += __shfl_xor_sync(0xffffffffu, lsum1, 1);
    lsum1 += __shfl_xor_sync(0xffffffffu, lsum1, 2);
    if ((l & 3) == 0) {
        g_l[bh*Sz + gq0] = lsum0;
        g_l[bh*Sz + gq1] = lsum1;
    }

    float pp0 = 0.f, pp1 = 0.f;
#pragma unroll
    for (int t = 0; t < 8; t++) {
        float a0 = cc[t][0], a1 = cc[t][1], a2 = cc[t][2], a3 = cc[t][3];
        float s0 = (t == 0 && (l & 3) == 0) ? -a0*a0 : a0*a0;
        float s2 = (t == 0 && (l & 3) == 0) ? -a2*a2 : a2*a2;
        pp0 += s0 + a1*a1;
        pp1 += s2 + a3*a3;
    }
    pp0 += __shfl_xor_sync(0xffffffffu, pp0, 1);
    pp0 += __shfl_xor_sync(0xffffffffu, pp0, 2);
    pp1 += __shfl_xor_sync(0xffffffffu, pp1, 1);
    pp1 += __shfl_xor_sync(0xffffffffu, pp1, 2);
    float inv0 = rsqrtf(fmaxf(fabsf(pp0), 1e-8f));
    float inv1 = rsqrtf(fmaxf(fabsf(pp1), 1e-8f));
    float* c0p = ctx + ((size_t)((b*Sz + gq0)*Hz + h)) * DPH + colq;
    float* c1p = ctx + ((size_t)((b*Sz + gq1)*Hz + h)) * DPH + colq;
#pragma unroll
    for (int t = 0; t < 8; t++) {
        *(float2*)(c0p + t*8) = make_float2(cc[t][0]*inv0, cc[t][1]*inv0);
        *(float2*)(c1p + t*8) = make_float2(cc[t][2]*inv1, cc[t][3]*inv1);
    }
}

// ---------------------------------------------------------------------------
// Attention pass 2: recompute S, write normalized attn. Zero tiles are stored
// FIRST (pure-BW stores overlap the initial Q/K loads); double-buffered K.
// ---------------------------------------------------------------------------
__global__ __launch_bounds__(256, 1) void pass2_kernel(
    float* __restrict__ attn, const float* __restrict__ scale_ptr)
{
    extern __shared__ char smraw[];
    const unsigned sb = (smem_u32(smraw) + 1023u) & ~1023u;

    const int blk = blockIdx.x;
    const int bh = blk & 15;
    const int qt = (NQT - 1) - (blk >> 4);
    const int q0 = qt * QT;

    const int tid = threadIdx.x;
    const int w = tid >> 5, l = tid & 31;

    const float inv_as = 1.f / scale_ptr[0];
    const __nv_bfloat16* Qhi = gPhi[0] + (size_t)bh * Sz * DPH;
    const __nv_bfloat16* Qlo = gPlo[0] + (size_t)bh * Sz * DPH;
    const __nv_bfloat16* Khi = gPhi[1] + (size_t)bh * Sz * DPH;
    const __nv_bfloat16* Klo = gPlo[1] + (size_t)bh * Sz * DPH;
    float* arow = attn + (size_t)bh * Sz * Sz;

    const int rr = tid >> 3, chk = tid & 7;

    auto issue_k = [&](int s, int kt) {
        unsigned base = sb + 32768u + (unsigned)s * 32768u;
        const int k0 = kt * QT;
#pragma unroll
        for (int it = 0; it < 4; it++) {
            int r = rr + it * 32;
            unsigned sw = SWZ((unsigned)(r * 128 + chk * 16));
            const size_t go = (size_t)(k0 + r) * DPH + chk * 8;
            cpa(base + sw,          Khi + go);
            cpa(base + 16384u + sw, Klo + go);
        }
        CP_COMMIT();
    };

#pragma unroll
    for (int it = 0; it < 4; it++) {
        int r = rr + it * 32;
        unsigned sw = SWZ((unsigned)(r * 128 + chk * 16));
        cpa(sb + sw,          Qhi + (size_t)(q0 + r) * DPH + chk * 8);
        cpa(sb + 16384u + sw, Qlo + (size_t)(q0 + r) * DPH + chk * 8);
    }
    CP_COMMIT();
    issue_k(0, 0);

    // zero the strict upper region FIRST: pure-BW stores overlap the loads
    {
        const int z0 = (qt + 1) * QT;
        const int nz4 = (Sz - z0) >> 2;
        if (nz4 > 0) {
            const float4 zero = make_float4(0.f, 0.f, 0.f, 0.f);
            for (int idx = tid; idx < 128 * nz4; idx += 256) {
                int r = idx / nz4, c = idx % nz4;
                *(float4*)(arow + (size_t)(q0 + r) * Sz + z0 + c * 4) = zero;
            }
        }
    }

    CP_WAIT(0);
    __syncthreads();

    unsigned qh[4][4], ql[4][4];
    {
        unsigned qoff = (unsigned)(w * 16 + (l & 15)) * 128 + ((l >> 4) * 16);
#pragma unroll
        for (int c = 0; c < 4; c++) {
            unsigned sw = SWZ(qoff + c * 32);
            ldsm4(sb + sw,          qh[c][0], qh[c][1], qh[c][2], qh[c][3]);
            ldsm4(sb + 16384u + sw, ql[c][0], ql[c][1], ql[c][2], ql[c][3]);
        }
    }

    const unsigned krow = (l & 7) + ((l & 16) >> 1);
    const unsigned kchalf = ((l >> 3) & 1) * 16;

    const int row0 = w * 16 + (l >> 2);
    const int gq0 = q0 + row0, gq1 = gq0 + 8;
    const int colq = (l & 3) * 2;
    const float il0 = 1.f / g_l[bh*Sz + gq0];
    const float il1 = 1.f / g_l[bh*Sz + gq1];

    for (int kt = 0; kt <= qt; ++kt) {
        const int k0 = kt * QT;
        if (kt < qt) { issue_k((kt + 1) & 1, kt + 1); CP_WAIT(1); }
        else         { CP_WAIT(0); }
        __syncthreads();
        const unsigned kb = sb + 32768u + (unsigned)(kt & 1) * 32768u;

        float sc[16][4];
#pragma unroll
        for (int i = 0; i < 16; i++)
#pragma unroll
            for (int j = 0; j < 4; j++) sc[i][j] = 0.f;
#pragma unroll
        for (int g = 0; g < 8; g++) {
            unsigned goff = (unsigned)(g * 16 + krow) * 128 + kchalf;
#pragma unroll
            for (int c = 0; c < 4; c++) {
                unsigned b0, b1, b2, b3, e0, e1, e2, e3;
                unsigned sw = SWZ(goff + c * 32);
                ldsm4(kb + sw,          b0, b1, b2, b3);
                ldsm4(kb + 16384u + sw, e0, e1, e2, e3);
                mma16816(sc[2*g],   qh[c], b0, b1);
                mma16816(sc[2*g+1], qh[c], b2, b3);
                mma16816(sc[2*g],   ql[c], b0, b1);
                mma16816(sc[2*g+1], ql[c], b2, b3);
                mma16816(sc[2*g],   qh[c], e0, e1);
                mma16816(sc[2*g+1], qh[c], e2, e3);
            }
        }

        const bool diag = (kt == qt);
        float* p0 = arow + (size_t)gq0 * Sz + k0 + colq;
        float* p1 = arow + (size_t)gq1 * Sz + k0 + colq;
#pragma unroll
        for (int t = 0; t < 16; t++) {
            int gk = k0 + t * 8 + colq;
            float v0 = __expf((2.f * sc[t][0] + 2.f) * inv_as) * il0;
            float v1 = __expf((2.f * sc[t][1] + 2.f) * inv_as) * il0;
            float v2 = __expf((2.f * sc[t][2] + 2.f) * inv_as) * il1;
            float v3 = __expf((2.f * sc[t][3] + 2.f) * inv_as) * il1;
            if (diag) {
                if (gk > gq0)     v0 = 0.f;
                if (gk + 1 > gq0) v1 = 0.f;
                if (gk > gq1)     v2 = 0.f;
                if (gk + 1 > gq1) v3 = 0.f;
            }
            *(float2*)(p0 + t*8) = make_float2(v0, v1);
            *(float2*)(p1 + t*8) = make_float2(v2, v3);
        }
        __syncthreads();
    }
}

extern "C" void kernel_launch(void* const* d_in, const int* in_sizes, int n_in,
                              void* d_out, int out_size)
{
    const float* key   = (const float*)d_in[0];
    const float* value = (const float*)d_in[1];
    const float* query = (const float*)d_in[2];
    const float* Wq = (const float*)d_in[4];
    const float* bq = (const float*)d_in[5];
    const float* sq = (const float*)d_in[6];
    const float* Wk = (const float*)d_in[7];
    const float* bk = (const float*)d_in[8];
    const float* sk = (const float*)d_in[9];
    const float* Wv = (const float*)d_in[10];
    const float* bv = (const float*)d_in[11];
    const float* sv = (const float*)d_in[12];
    const float* att_scale = (const float*)d_in[13];

    float* ctx  = (float*)d_out;
    float* attn = ctx + (size_t)Bz * Sz * Dz;

    dim3 gs(512, 6);
    split_kernel<<<gs, 256>>>(query, key, value, Wq, Wk, Wv);

    cudaFuncSetAttribute(proj_kernel, cudaFuncAttributeMaxDynamicSharedMemorySize, SMEM_PROJ);
    dim3 gp(Dz / 128, Mrows / 128, 3);
    proj_kernel<<<gp, 256, SMEM_PROJ>>>(bq, sq, bk, sk, bv, sv);

    cudaFuncSetAttribute(attn_kernel, cudaFuncAttributeMaxDynamicSharedMemorySize, SMEM_ATTN);
    attn_kernel<<<BHn * NQT, 256, SMEM_ATTN>>>(ctx, att_scale);

    cudaFuncSetAttribute(pass2_kernel, cudaFuncAttributeMaxDynamicSharedMemorySize, SMEM_P2);
    pass2_kernel<<<BHn * NQT, 256, SMEM_P2>>>(attn, att_scale);
}